// round 1
// baseline (speedup 1.0000x reference)
#include <cuda_runtime.h>
#include <cstdint>

typedef unsigned long long ull;

// ---- f32x2 packed helpers (sm_100+ PTX) ------------------------------------

__device__ __forceinline__ ull pack2(float lo, float hi) {
    ull r;
    asm("mov.b64 %0, {%1, %2};" : "=l"(r) : "f"(lo), "f"(hi));
    return r;
}

// {a.hi, b.lo} — the misaligned middle pair, one register re-pairing
__device__ __forceinline__ ull midpair(ull a, ull b) {
    ull r;
    asm("{\n\t"
        ".reg .b32 alo, ahi, blo, bhi;\n\t"
        "mov.b64 {alo, ahi}, %1;\n\t"
        "mov.b64 {blo, bhi}, %2;\n\t"
        "mov.b64 %0, {ahi, blo};\n\t"
        "}"
        : "=l"(r) : "l"(a), "l"(b));
    return r;
}

// d += a * b on packed f32x2
__device__ __forceinline__ void fma2(ull& d, ull a, ull b) {
    asm("fma.rn.f32x2 %0, %1, %2, %0;" : "+l"(d) : "l"(a), "l"(b));
}

// ---- kernel -----------------------------------------------------------------

#define C_CH   64
#define H_IN   512
#define W_IN   512
#define H_OUT  510
#define W_OUT  510
#define TY     10          // output rows per thread (510 % 10 == 0 -> 51 tiles)
#define BLK_X  128         // threads per block, each owns one x-pair

__global__ void __launch_bounds__(BLK_X)
dwconv3x3_f32x2_kernel(const float* __restrict__ x,
                       const float* __restrict__ w,
                       float* __restrict__ out)
{
    const int pair = blockIdx.x * BLK_X + threadIdx.x;  // 0..254 valid
    const int ox   = pair * 2;                          // even output x
    if (ox >= W_OUT) return;                            // guards pair==255

    const int oy0   = blockIdx.y * TY;
    const int plane = blockIdx.z;                       // n*C + c
    const int c     = plane & (C_CH - 1);

    // Splat the 9 channel weights into packed f32x2 registers.
    const float* wp = w + c * 9;
    ull wv[9];
#pragma unroll
    for (int i = 0; i < 9; ++i) {
        const float wf = __ldg(wp + i);
        wv[i] = pack2(wf, wf);
    }

    const float* ip = x   + (size_t)plane * (H_IN * W_IN);
    float*       op = out + (size_t)plane * (H_OUT * W_OUT);

    ull acc[TY];
#pragma unroll
    for (int o = 0; o < TY; ++o) acc[o] = 0ull;   // bit pattern 0 == (0.f, 0.f)

    // Sliding window over TY+2 input rows. Input row r (absolute oy0+r)
    // feeds outputs o = r-2, r-1, r with ky = r-o.
#pragma unroll
    for (int r = 0; r < TY + 2; ++r) {
        const float* row = ip + (size_t)(oy0 + r) * W_IN + ox;
        const ull A = *reinterpret_cast<const ull*>(row);      // (i0, i1) aligned
        const ull B = *reinterpret_cast<const ull*>(row + 2);  // (i2, i3) aligned
        const ull M = midpair(A, B);                           // (i1, i2)

#pragma unroll
        for (int ky = 0; ky < 3; ++ky) {
            const int o = r - ky;
            if (o >= 0 && o < TY) {
                fma2(acc[o], wv[ky * 3 + 0], A);
                fma2(acc[o], wv[ky * 3 + 1], M);
                fma2(acc[o], wv[ky * 3 + 2], B);
            }
        }
    }

#pragma unroll
    for (int o = 0; o < TY; ++o) {
        *reinterpret_cast<ull*>(op + (size_t)(oy0 + o) * W_OUT + ox) = acc[o];
    }
}

// ---- launch -----------------------------------------------------------------

extern "C" void kernel_launch(void* const* d_in, const int* in_sizes, int n_in,
                              void* d_out, int out_size)
{
    const float* x   = (const float*)d_in[0];   // (16, 64, 512, 512) fp32
    const float* w   = (const float*)d_in[1];   // (64, 3, 3) fp32
    float*       out = (float*)d_out;           // (16, 64, 510, 510) fp32

    // x-pairs: 255 -> 2 blocks of 128; y: 51 tiles of 10 rows; z: 16*64 planes
    dim3 grid(2, H_OUT / TY, 16 * C_CH);
    dim3 block(BLK_X);
    dwconv3x3_f32x2_kernel<<<grid, block>>>(x, w, out);
}

// round 2
// speedup vs baseline: 1.1284x; 1.1284x over previous
#include <cuda_runtime.h>
#include <cstdint>

typedef unsigned long long ull;

// ---- f32x2 packed helpers (sm_100+ PTX) ------------------------------------

__device__ __forceinline__ ull pack2(float lo, float hi) {
    ull r;
    asm("mov.b64 %0, {%1, %2};" : "=l"(r) : "f"(lo), "f"(hi));
    return r;
}

// {a.hi, b.lo} — middle pair, register re-pairing only
__device__ __forceinline__ ull midpair(ull a, ull b) {
    ull r;
    asm("{\n\t"
        ".reg .b32 alo, ahi, blo, bhi;\n\t"
        "mov.b64 {alo, ahi}, %1;\n\t"
        "mov.b64 {blo, bhi}, %2;\n\t"
        "mov.b64 %0, {ahi, blo};\n\t"
        "}"
        : "=l"(r) : "l"(a), "l"(b));
    return r;
}

// d += a * b on packed f32x2
__device__ __forceinline__ void fma2(ull& d, ull a, ull b) {
    asm("fma.rn.f32x2 %0, %1, %2, %0;" : "+l"(d) : "l"(a), "l"(b));
}

// ---- kernel -----------------------------------------------------------------

#define C_CH   64
#define H_IN   512
#define W_IN   512
#define H_OUT  510
#define W_OUT  510
#define TY     15                 // output rows per CTA tile (510 = 34*15)
#define ROWS   (TY + 2)           // input rows staged in smem
#define NTHR   256

__global__ void __launch_bounds__(NTHR, 4)
dwconv3x3_smem_kernel(const float* __restrict__ x,
                      const float* __restrict__ w,
                      float* __restrict__ out)
{
    __shared__ float s[ROWS * W_IN];   // 17*512*4 = 34816 B

    const int tid   = threadIdx.x;
    const int ytile = blockIdx.x;      // 0..33
    const int plane = blockIdx.y;      // n*C + c, 0..1023
    const int c     = plane & (C_CH - 1);
    const int iy0   = ytile * TY;      // first input row of tile

    // ---- cooperative, fully coalesced tile load (float4 streams) ----
    {
        const float4* g = reinterpret_cast<const float4*>(
            x + (size_t)plane * (H_IN * W_IN) + (size_t)iy0 * W_IN);
        float4* sv = reinterpret_cast<float4*>(s);
        const int total4 = ROWS * W_IN / 4;    // 2176
#pragma unroll
        for (int k = tid; k < total4; k += NTHR)
            sv[k] = g[k];
    }

    // ---- weights: splat 9 taps into packed f32x2 ----
    const float* wp = w + c * 9;
    ull wv[9];
#pragma unroll
    for (int i = 0; i < 9; ++i) {
        const float wf = __ldg(wp + i);
        wv[i] = pack2(wf, wf);
    }

    __syncthreads();

    // ---- compute: thread t owns output x-pair (2t, 2t+1), rows 0..TY-1 ----
    if (tid < W_OUT / 2) {             // 255 compute threads, 1 idle
        ull acc[TY];
#pragma unroll
        for (int o = 0; o < TY; ++o) acc[o] = 0ull;

#pragma unroll
        for (int r = 0; r < ROWS; ++r) {
            const float* srow = s + r * W_IN + 2 * tid;
            const ull A = *reinterpret_cast<const ull*>(srow);      // (i0,i1)
            const ull B = *reinterpret_cast<const ull*>(srow + 2);  // (i2,i3)
            const ull M = midpair(A, B);                            // (i1,i2)

#pragma unroll
            for (int ky = 0; ky < 3; ++ky) {
                const int o = r - ky;
                if (o >= 0 && o < TY) {
                    fma2(acc[o], wv[ky * 3 + 0], A);
                    fma2(acc[o], wv[ky * 3 + 1], M);
                    fma2(acc[o], wv[ky * 3 + 2], B);
                }
            }
        }

        float* op = out + (size_t)plane * (H_OUT * W_OUT)
                        + (size_t)iy0 * W_OUT + 2 * tid;
#pragma unroll
        for (int o = 0; o < TY; ++o)
            *reinterpret_cast<ull*>(op + (size_t)o * W_OUT) = acc[o];
    }
}

// ---- launch -----------------------------------------------------------------

extern "C" void kernel_launch(void* const* d_in, const int* in_sizes, int n_in,
                              void* d_out, int out_size)
{
    const float* x   = (const float*)d_in[0];   // (16, 64, 512, 512) fp32
    const float* w   = (const float*)d_in[1];   // (64, 3, 3) fp32
    float*       out = (float*)d_out;           // (16, 64, 510, 510) fp32

    dim3 grid(H_OUT / TY, 16 * C_CH);           // (34, 1024)
    dim3 block(NTHR);
    dwconv3x3_smem_kernel<<<grid, block>>>(x, w, out);
}